// round 11
// baseline (speedup 1.0000x reference)
#include <cuda_runtime.h>
#include <cuda_bf16.h>

#define NB 4
#define NS 2048
#define NE 1024
#define NH 16
#define ND 64
#define NM (NB*NS)          // 8192 rows

// ---------------------------------------------------------------------------
// Device-global scratch (allocation-free rule). All bf16 hi/lo pairs.
// ---------------------------------------------------------------------------
__device__ __nv_bfloat16 g_xhi[(size_t)NM*NE];
__device__ __nv_bfloat16 g_xlo[(size_t)NM*NE];
__device__ __nv_bfloat16 g_whi[(size_t)4*NE*NE];   // q,k,v,o
__device__ __nv_bfloat16 g_wlo[(size_t)4*NE*NE];
__device__ __nv_bfloat16 g_qhi[(size_t)NM*NE];     // [B,H,S,D]
__device__ __nv_bfloat16 g_qlo[(size_t)NM*NE];
__device__ __nv_bfloat16 g_khi[(size_t)NM*NE];
__device__ __nv_bfloat16 g_klo[(size_t)NM*NE];
__device__ __nv_bfloat16 g_vhi[(size_t)NM*NE];
__device__ __nv_bfloat16 g_vlo[(size_t)NM*NE];
__device__ __nv_bfloat16 g_chi[(size_t)NM*NE];     // ctx [B,S,E]
__device__ __nv_bfloat16 g_clo[(size_t)NM*NE];

// ---------------------------------------------------------------------------
// Helpers
// ---------------------------------------------------------------------------
__device__ __forceinline__ unsigned smem_u32(const void* p) {
    unsigned a;
    asm("{ .reg .u64 t; cvta.to.shared.u64 t, %1; cvt.u32.u64 %0, t; }"
        : "=r"(a) : "l"(p));
    return a;
}
#define SW128(o) ((o) ^ (((o) >> 3) & 0x70))

__device__ __forceinline__ void ldm4(unsigned* r, unsigned addr) {
    asm volatile("ldmatrix.sync.aligned.m8n8.x4.shared.b16 {%0,%1,%2,%3}, [%4];"
                 : "=r"(r[0]), "=r"(r[1]), "=r"(r[2]), "=r"(r[3]) : "r"(addr));
}
__device__ __forceinline__ void ldm4t(unsigned* r, unsigned addr) {
    asm volatile("ldmatrix.sync.aligned.m8n8.x4.trans.shared.b16 {%0,%1,%2,%3}, [%4];"
                 : "=r"(r[0]), "=r"(r[1]), "=r"(r[2]), "=r"(r[3]) : "r"(addr));
}
__device__ __forceinline__ void mma16816(float* d, unsigned a0, unsigned a1,
                                         unsigned a2, unsigned a3,
                                         unsigned b0, unsigned b1) {
    asm volatile(
        "mma.sync.aligned.m16n8k16.row.col.f32.bf16.bf16.f32 "
        "{%0,%1,%2,%3}, {%4,%5,%6,%7}, {%8,%9}, {%0,%1,%2,%3};"
        : "+f"(d[0]), "+f"(d[1]), "+f"(d[2]), "+f"(d[3])
        : "r"(a0), "r"(a1), "r"(a2), "r"(a3), "r"(b0), "r"(b1));
}
#define CP_ASYNC16(dst, src) \
    asm volatile("cp.async.cg.shared.global [%0], [%1], 16;" :: "r"(dst), "l"(src))
#define CP_COMMIT() asm volatile("cp.async.commit_group;" ::: "memory")
#define CP_WAIT(n)  asm volatile("cp.async.wait_group %0;" :: "n"(n) : "memory")

__device__ __forceinline__ unsigned pack_bf2(float lo, float hi) {
    __nv_bfloat162 t = __floats2bfloat162_rn(lo, hi);
    return *(unsigned*)&t;
}
__device__ __forceinline__ float ex2(float x) {
    float y;
    asm("ex2.approx.f32 %0, %1;" : "=f"(y) : "f"(x));
    return y;
}

// ---------------------------------------------------------------------------
// fp32 -> bf16 hi/lo splits
// ---------------------------------------------------------------------------
__global__ __launch_bounds__(256)
void split_x_kernel(const float* __restrict__ src)
{
    size_t i = ((size_t)blockIdx.x * 256 + threadIdx.x) * 4;
    float4 v = *(const float4*)(src + i);
    __nv_bfloat16 h0 = __float2bfloat16(v.x), h1 = __float2bfloat16(v.y);
    __nv_bfloat16 h2 = __float2bfloat16(v.z), h3 = __float2bfloat16(v.w);
    *(__nv_bfloat162*)(g_xhi + i)     = __halves2bfloat162(h0, h1);
    *(__nv_bfloat162*)(g_xhi + i + 2) = __halves2bfloat162(h2, h3);
    *(__nv_bfloat162*)(g_xlo + i)     = __halves2bfloat162(
        __float2bfloat16(v.x - __bfloat162float(h0)),
        __float2bfloat16(v.y - __bfloat162float(h1)));
    *(__nv_bfloat162*)(g_xlo + i + 2) = __halves2bfloat162(
        __float2bfloat16(v.z - __bfloat162float(h2)),
        __float2bfloat16(v.w - __bfloat162float(h3)));
}

__global__ __launch_bounds__(256)
void split_w_kernel(const float* __restrict__ Wq, const float* __restrict__ Wk,
                    const float* __restrict__ Wv, const float* __restrict__ Wo)
{
    const float* src = (blockIdx.y == 0) ? Wq : (blockIdx.y == 1) ? Wk
                     : (blockIdx.y == 2) ? Wv : Wo;
    __nv_bfloat16* hi = g_whi + (size_t)blockIdx.y * NE * NE;
    __nv_bfloat16* lo = g_wlo + (size_t)blockIdx.y * NE * NE;
    size_t i = ((size_t)blockIdx.x * 256 + threadIdx.x) * 4;
    float4 v = *(const float4*)(src + i);
    __nv_bfloat16 h0 = __float2bfloat16(v.x), h1 = __float2bfloat16(v.y);
    __nv_bfloat16 h2 = __float2bfloat16(v.z), h3 = __float2bfloat16(v.w);
    *(__nv_bfloat162*)(hi + i)     = __halves2bfloat162(h0, h1);
    *(__nv_bfloat162*)(hi + i + 2) = __halves2bfloat162(h2, h3);
    *(__nv_bfloat162*)(lo + i)     = __halves2bfloat162(
        __float2bfloat16(v.x - __bfloat162float(h0)),
        __float2bfloat16(v.y - __bfloat162float(h1)));
    *(__nv_bfloat162*)(lo + i + 2) = __halves2bfloat162(
        __float2bfloat16(v.z - __bfloat162float(h2)),
        __float2bfloat16(v.w - __bfloat162float(h3)));
}

// ---------------------------------------------------------------------------
// mma.sync NT-GEMM: C[128x128] = A[128xK] @ W[128xK]^T, 3xBF16 split.
// 512 thr = 16 warps (4m x 4n), warp tile 32x32. 3-stage cp.async pipeline.
// ---------------------------------------------------------------------------
#define MM_TILE  16384                 // 128 rows x 128 bytes
#define MM_STAGE (4 * MM_TILE)         // Ah, Al, Bh, Bl (64 KB)
#define MM_SMEM  (3 * MM_STAGE)        // 192 KB, 3 stages

__global__ __launch_bounds__(512, 1)
void mm_tc(int mode, const float* __restrict__ bias0, const float* __restrict__ bias1,
           const float* __restrict__ bias2, float* __restrict__ outp)
{
    extern __shared__ char sm[];
    const unsigned smb = smem_u32(sm);
    const int tid = threadIdx.x;
    const int lane = tid & 31, w = tid >> 5;
    const int wm = w & 3, wn = w >> 2;

    const int z  = (mode == 0) ? (int)blockIdx.z : 3;
    const int m0 = blockIdx.x * 128;
    const int n0 = blockIdx.y * 128;

    const __nv_bfloat16* Ahi = (mode == 0) ? g_xhi : g_chi;
    const __nv_bfloat16* Alo = (mode == 0) ? g_xlo : g_clo;
    const __nv_bfloat16* Bhi = g_whi + (size_t)z * NE * NE;
    const __nv_bfloat16* Blo = g_wlo + (size_t)z * NE * NE;

    const __nv_bfloat16* gp[4] = {
        Ahi + (size_t)m0 * NE, Alo + (size_t)m0 * NE,
        Bhi + (size_t)n0 * NE, Blo + (size_t)n0 * NE };

    float acc[2][4][4];
    #pragma unroll
    for (int mt = 0; mt < 2; mt++)
        #pragma unroll
        for (int nt = 0; nt < 4; nt++)
            #pragma unroll
            for (int q = 0; q < 4; q++) acc[mt][nt][q] = 0.f;

    auto load_chunk = [&](int buf, int k0) {
        const unsigned sb = smb + buf * MM_STAGE;
        #pragma unroll
        for (int t = 0; t < 4; t++)
            #pragma unroll
            for (int i = 0; i < 2; i++) {
                int e = tid + i * 512;
                int r = e >> 3, c = e & 7;
                CP_ASYNC16(sb + t * MM_TILE + SW128(r * 128 + c * 16),
                           gp[t] + (size_t)r * NE + k0 + c * 8);
            }
    };

    load_chunk(0, 0);    CP_COMMIT();
    load_chunk(1, 64);   CP_COMMIT();
    load_chunk(2, 128);  CP_COMMIT();

    int st = 0;
    #pragma unroll 1
    for (int ch = 0; ch < 16; ch++) {
        CP_WAIT(2);
        __syncthreads();

        const unsigned ab = smb + st * MM_STAGE;
        #pragma unroll
        for (int ks = 0; ks < 4; ks++) {
            const unsigned kb = ks * 32 + ((lane >> 4) << 4);
            unsigned ah[2][4], al[2][4];
            #pragma unroll
            for (int mt = 0; mt < 2; mt++) {
                unsigned row = wm * 32 + mt * 16 + (lane & 15);
                unsigned so = SW128(row * 128 + kb);
                ldm4(ah[mt], ab + so);
                ldm4(al[mt], ab + MM_TILE + so);
            }
            unsigned bh0[4], bh1[4], bl0[4], bl1[4];
            #pragma unroll
            for (int np = 0; np < 2; np++) {
                unsigned row = wn * 32 + np * 16 + (lane & 15);
                unsigned so = SW128(row * 128 + kb);
                unsigned r[4];
                ldm4(r, ab + 2 * MM_TILE + so);
                bh0[2*np] = r[0]; bh1[2*np] = r[2];
                bh0[2*np+1] = r[1]; bh1[2*np+1] = r[3];
                ldm4(r, ab + 3 * MM_TILE + so);
                bl0[2*np] = r[0]; bl1[2*np] = r[2];
                bl0[2*np+1] = r[1]; bl1[2*np+1] = r[3];
            }
            #pragma unroll
            for (int mt = 0; mt < 2; mt++)
                #pragma unroll
                for (int nt = 0; nt < 4; nt++) {
                    mma16816(acc[mt][nt], ah[mt][0], ah[mt][1], ah[mt][2], ah[mt][3],
                             bh0[nt], bh1[nt]);
                    mma16816(acc[mt][nt], ah[mt][0], ah[mt][1], ah[mt][2], ah[mt][3],
                             bl0[nt], bl1[nt]);
                    mma16816(acc[mt][nt], al[mt][0], al[mt][1], al[mt][2], al[mt][3],
                             bh0[nt], bh1[nt]);
                }
        }

        __syncthreads();
        if (ch + 3 < 16) load_chunk(st, (ch + 3) * 64);
        CP_COMMIT();
        st = (st == 2) ? 0 : st + 1;
    }

    const int g = lane >> 2, c4 = lane & 3;
    #pragma unroll
    for (int mt = 0; mt < 2; mt++) {
        #pragma unroll
        for (int nt = 0; nt < 4; nt++) {
            const int n = n0 + wn * 32 + nt * 8 + 2 * c4;
            const float2 b2 = *(const float2*)&((mode == 1) ? bias0
                                : (z == 0) ? bias0 : (z == 1) ? bias1 : bias2)[n];
            #pragma unroll
            for (int hrow = 0; hrow < 2; hrow++) {
                const int m = m0 + wm * 32 + mt * 16 + g + hrow * 8;
                float v0 = acc[mt][nt][2*hrow + 0] + b2.x;
                float v1 = acc[mt][nt][2*hrow + 1] + b2.y;
                if (mode == 1) {
                    *(float2*)&outp[(size_t)m * NE + n] = make_float2(v0, v1);
                } else {
                    __nv_bfloat16 h0 = __float2bfloat16(v0);
                    __nv_bfloat16 h1 = __float2bfloat16(v1);
                    const int bb = m >> 11, s = m & (NS - 1);
                    const int hh = n >> 6, d = n & 63;
                    size_t idx = (((size_t)(bb * NH + hh)) * NS + s) * ND + d;
                    __nv_bfloat16 *hp, *lp;
                    if (z == 0)      { hp = g_qhi; lp = g_qlo; }
                    else if (z == 1) { hp = g_khi; lp = g_klo; }
                    else             { hp = g_vhi; lp = g_vlo; }
                    *(__nv_bfloat162*)&hp[idx] = __halves2bfloat162(h0, h1);
                    *(__nv_bfloat162*)&lp[idx] = __halves2bfloat162(
                        __float2bfloat16(v0 - __bfloat162float(h0)),
                        __float2bfloat16(v1 - __bfloat162float(h1)));
                }
            }
        }
    }
}

// ---------------------------------------------------------------------------
// Flash attention, 512 thr = 16 warps. Warp (qg8, kh): 16 q-rows x 32 k-cols
// (split-k over 2 warps — legal because no-max softmax has no row coupling;
// partial O and l merged once through smem at the end).
// 3-stage cp.async K/V pipeline. NO-MAX softmax.
// ---------------------------------------------------------------------------
#define AT_QH 0
#define AT_QL 16384
#define AT_KV 32768
#define AT_KVSTAGE 32768               // KH, KL, VH, VL (8KB each)
#define AT_MASK (AT_KV + 3 * AT_KVSTAGE)
#define AT_SMEM (AT_MASK + 3 * 256 + 16)

__global__ __launch_bounds__(512, 1)
void attn_kernel(const int* __restrict__ amask)
{
    extern __shared__ char sm[];
    const unsigned smb = smem_u32(sm);

    const int tid = threadIdx.x;
    const int lane = tid & 31, w = tid >> 5;
    const int qg8 = w >> 1, kh = w & 1;
    const int g = lane >> 2, c4 = lane & 3;
    const int b = blockIdx.z, h = blockIdx.y;
    const int q0 = blockIdx.x * 128;

    const size_t bh_off = ((size_t)(b * NH + h)) * NS * ND;
    const __nv_bfloat16* Qh = g_qhi + bh_off + (size_t)q0 * ND;
    const __nv_bfloat16* Ql = g_qlo + bh_off + (size_t)q0 * ND;
    const __nv_bfloat16* Kp[4] = { g_khi + bh_off, g_klo + bh_off,
                                   g_vhi + bh_off, g_vlo + bh_off };
    const int* amp = amask + b * NS;

    auto issue_kv = [&](int stage, int k0) {
        const unsigned sb = smb + AT_KV + stage * AT_KVSTAGE;
        #pragma unroll
        for (int t = 0; t < 4; t++) {
            int r = tid >> 3, c = tid & 7;
            CP_ASYNC16(sb + t * 8192 + SW128(r * 128 + c * 16),
                       Kp[t] + (size_t)(k0 + r) * 64 + c * 8);
        }
        if (tid < 16)
            CP_ASYNC16(smb + AT_MASK + stage * 256 + tid * 16,
                       amp + k0 + tid * 4);
    };

    issue_kv(0, 0);    CP_COMMIT();
    issue_kv(1, 64);   CP_COMMIT();
    issue_kv(2, 128);  CP_COMMIT();

    #pragma unroll
    for (int i = 0; i < 2; i++) {
        int e = tid + i * 512;
        int r = e >> 3, c = e & 7;
        unsigned so = SW128(r * 128 + c * 16);
        *(uint4*)(sm + AT_QH + so) = *(const uint4*)(Qh + (size_t)r * 64 + c * 8);
        *(uint4*)(sm + AT_QL + so) = *(const uint4*)(Ql + (size_t)r * 64 + c * 8);
    }
    __syncthreads();

    const float SC = 0.125f * 1.44269504088896f;   // /sqrt(64) * log2(e)
    float l0 = 0.f, l1 = 0.f;
    float o[8][4];
    #pragma unroll
    for (int nt = 0; nt < 8; nt++)
        #pragma unroll
        for (int q = 0; q < 4; q++) o[nt][q] = 0.f;

    const unsigned qrow = qg8 * 16 + (lane & 15);

    int st = 0;
    #pragma unroll 1
    for (int kt = 0; kt < NS / 64; kt++) {
        const unsigned kvb = smb + AT_KV + st * AT_KVSTAGE;
        CP_WAIT(2);
        __syncthreads();

        // ---- S = Q K^T (own 32 k-cols) ----
        float s[4][4];
        #pragma unroll
        for (int nt = 0; nt < 4; nt++)
            #pragma unroll
            for (int q = 0; q < 4; q++) s[nt][q] = 0.f;

        #pragma unroll
        for (int ks = 0; ks < 4; ks++) {
            const unsigned kb = ks * 32 + ((lane >> 4) << 4);
            const unsigned qso = SW128(qrow * 128 + kb);
            unsigned qh[4], ql[4];
            ldm4(qh, smb + AT_QH + qso);
            ldm4(ql, smb + AT_QL + qso);
            unsigned bh0[4], bh1[4], bl0[4], bl1[4];
            #pragma unroll
            for (int np = 0; np < 2; np++) {
                unsigned nrow = kh * 32 + np * 16 + (lane & 15);
                unsigned so = SW128(nrow * 128 + kb);
                unsigned r[4];
                ldm4(r, kvb + so);
                bh0[2*np] = r[0]; bh1[2*np] = r[2];
                bh0[2*np+1] = r[1]; bh1[2*np+1] = r[3];
                ldm4(r, kvb + 8192 + so);
                bl0[2*np] = r[0]; bl1[2*np] = r[2];
                bl0[2*np+1] = r[1]; bl1[2*np+1] = r[3];
            }
            #pragma unroll
            for (int nt = 0; nt < 4; nt++) {
                mma16816(s[nt], qh[0], qh[1], qh[2], qh[3], bh0[nt], bh1[nt]);
                mma16816(s[nt], qh[0], qh[1], qh[2], qh[3], bl0[nt], bl1[nt]);
                mma16816(s[nt], ql[0], ql[1], ql[2], ql[3], bh0[nt], bh1[nt]);
            }
        }

        // ---- no-max softmax on own half ----
        const int* smask = (const int*)(sm + AT_MASK + st * 256) + kh * 32;
        unsigned pg_hi[4], pg8_hi[4], pg_lo[4], pg8_lo[4];
        #pragma unroll
        for (int nt = 0; nt < 4; nt++) {
            float mA = smask[nt * 8 + 2 * c4]     ? 0.f : -1e30f;
            float mB = smask[nt * 8 + 2 * c4 + 1] ? 0.f : -1e30f;
            float p0 = ex2(fmaf(s[nt][0], SC, mA));
            float p1 = ex2(fmaf(s[nt][1], SC, mB));
            float p2 = ex2(fmaf(s[nt][2], SC, mA));
            float p3 = ex2(fmaf(s[nt][3], SC, mB));
            l0 += p0 + p1;
            l1 += p2 + p3;
            unsigned u0 = __float_as_uint(p0), u1 = __float_as_uint(p1);
            unsigned u2 = __float_as_uint(p2), u3 = __float_as_uint(p3);
            pg_hi[nt]  = __byte_perm(u0, u1, 0x7632);   // truncated bf16 pair
            pg8_hi[nt] = __byte_perm(u2, u3, 0x7632);
            pg_lo[nt]  = pack_bf2(p0 - __uint_as_float(u0 & 0xffff0000u),
                                  p1 - __uint_as_float(u1 & 0xffff0000u));
            pg8_lo[nt] = pack_bf2(p2 - __uint_as_float(u2 & 0xffff0000u),
                                  p3 - __uint_as_float(u3 & 0xffff0000u));
        }

        // ---- O += P V (own 32 k-rows of V, full d=64) ----
        #pragma unroll
        for (int j = 0; j < 2; j++) {
            unsigned vh0[8], vh1[8], vl0[8], vl1[8];
            #pragma unroll
            for (int dp = 0; dp < 4; dp++) {
                unsigned krow = kh * 32 + j * 16 + (lane & 7) + ((lane >> 4) << 3);
                unsigned dby  = dp * 32 + (((lane >> 3) & 1) << 4);
                unsigned so = SW128(krow * 128 + dby);
                unsigned r[4];
                ldm4t(r, kvb + 16384 + so);
                vh0[2*dp] = r[0]; vh1[2*dp] = r[2];
                vh0[2*dp+1] = r[1]; vh1[2*dp+1] = r[3];
                ldm4t(r, kvb + 24576 + so);
                vl0[2*dp] = r[0]; vl1[2*dp] = r[2];
                vl0[2*dp+1] = r[1]; vl1[2*dp+1] = r[3];
            }
            #pragma unroll
            for (int nt = 0; nt < 8; nt++) {
                mma16816(o[nt], pg_hi[2*j], pg8_hi[2*j], pg_hi[2*j+1], pg8_hi[2*j+1],
                         vh0[nt], vh1[nt]);
                mma16816(o[nt], pg_hi[2*j], pg8_hi[2*j], pg_hi[2*j+1], pg8_hi[2*j+1],
                         vl0[nt], vl1[nt]);
                mma16816(o[nt], pg_lo[2*j], pg8_lo[2*j], pg_lo[2*j+1], pg8_lo[2*j+1],
                         vh0[nt], vh1[nt]);
            }
        }

        __syncthreads();
        if (kt + 3 < NS / 64) issue_kv(st, (kt + 3) * 64);
        CP_COMMIT();
        st = (st == 2) ? 0 : st + 1;
    }

    // ---- merge the two k-halves through smem (reuse KV region) ----
    float* rbuf = (float*)(sm + AT_KV);
    if (kh == 1) {
        float* dst = rbuf + ((size_t)(qg8 * 32 + lane)) * 34;
        #pragma unroll
        for (int nt = 0; nt < 8; nt++)
            #pragma unroll
            for (int q = 0; q < 4; q++) dst[nt * 4 + q] = o[nt][q];
        dst[32] = l0; dst[33] = l1;
    }
    __syncthreads();
    if (kh == 0) {
        const float* src = rbuf + ((size_t)(qg8 * 32 + lane)) * 34;
        #pragma unroll
        for (int nt = 0; nt < 8; nt++)
            #pragma unroll
            for (int q = 0; q < 4; q++) o[nt][q] += src[nt * 4 + q];
        l0 += src[32]; l1 += src[33];

        #pragma unroll
        for (int off = 1; off <= 2; off <<= 1) {
            l0 += __shfl_xor_sync(0xffffffffu, l0, off);
            l1 += __shfl_xor_sync(0xffffffffu, l1, off);
        }
        const float inv0 = 1.0f / l0;
        const float inv1 = 1.0f / l1;
        const int qg = q0 + qg8 * 16 + g;
        #pragma unroll
        for (int nt = 0; nt < 8; nt++) {
            const int col = h * ND + nt * 8 + 2 * c4;
            {
                float v0 = o[nt][0] * inv0, v1 = o[nt][1] * inv0;
                __nv_bfloat16 h0 = __float2bfloat16(v0), h1 = __float2bfloat16(v1);
                size_t idx = ((size_t)(b * NS + qg)) * NE + col;
                *(__nv_bfloat162*)&g_chi[idx] = __halves2bfloat162(h0, h1);
                *(__nv_bfloat162*)&g_clo[idx] = __halves2bfloat162(
                    __float2bfloat16(v0 - __bfloat162float(h0)),
                    __float2bfloat16(v1 - __bfloat162float(h1)));
            }
            {
                float v0 = o[nt][2] * inv1, v1 = o[nt][3] * inv1;
                __nv_bfloat16 h0 = __float2bfloat16(v0), h1 = __float2bfloat16(v1);
                size_t idx = ((size_t)(b * NS + qg + 8)) * NE + col;
                *(__nv_bfloat162*)&g_chi[idx] = __halves2bfloat162(h0, h1);
                *(__nv_bfloat162*)&g_clo[idx] = __halves2bfloat162(
                    __float2bfloat16(v0 - __bfloat162float(h0)),
                    __float2bfloat16(v1 - __bfloat162float(h1)));
            }
        }
    }
}

// ---------------------------------------------------------------------------

extern "C" void kernel_launch(void* const* d_in, const int* in_sizes, int n_in,
                              void* d_out, int out_size)
{
    const float* x   = (const float*)d_in[0];
    const int*   am  = (const int*)  d_in[1];
    const float* Wq  = (const float*)d_in[2];
    const float* bq  = (const float*)d_in[3];
    const float* Wk  = (const float*)d_in[4];
    const float* bk  = (const float*)d_in[5];
    const float* Wv  = (const float*)d_in[6];
    const float* bv  = (const float*)d_in[7];
    const float* Wo  = (const float*)d_in[8];
    const float* bo  = (const float*)d_in[9];
    float* out = (float*)d_out;

    cudaFuncSetAttribute(mm_tc, cudaFuncAttributeMaxDynamicSharedMemorySize, MM_SMEM);
    cudaFuncSetAttribute(attn_kernel, cudaFuncAttributeMaxDynamicSharedMemorySize, AT_SMEM);

    split_x_kernel<<<NM * NE / 1024, 256>>>(x);
    split_w_kernel<<<dim3(NE * NE / 1024, 4), 256>>>(Wq, Wk, Wv, Wo);

    mm_tc<<<dim3(NM / 128, NE / 128, 3), 512, MM_SMEM>>>(0, bq, bk, bv, nullptr);

    attn_kernel<<<dim3(NS / 128, NH, NB), 512, AT_SMEM>>>(am);

    mm_tc<<<dim3(NM / 128, NE / 128, 1), 512, MM_SMEM>>>(1, bo, nullptr, nullptr, out);
}

// round 13
// speedup vs baseline: 1.3997x; 1.3997x over previous
#include <cuda_runtime.h>
#include <cuda_bf16.h>
#include <cuda_fp16.h>

#define NB 4
#define NS 2048
#define NE 1024
#define NH 16
#define ND 64
#define NM (NB*NS)          // 8192 rows

// ---------------------------------------------------------------------------
// Device-global scratch (allocation-free rule).
// ---------------------------------------------------------------------------
__device__ __nv_bfloat16 g_xhi[(size_t)NM*NE];
__device__ __nv_bfloat16 g_xlo[(size_t)NM*NE];
__device__ __nv_bfloat16 g_whi[(size_t)4*NE*NE];   // q,k,v,o
__device__ __nv_bfloat16 g_wlo[(size_t)4*NE*NE];
__device__ __half        g_q16[(size_t)NM*NE];     // [B,H,S,D] fp16 single
__device__ __half        g_k16[(size_t)NM*NE];
__device__ __half        g_v16[(size_t)NM*NE];
__device__ __nv_bfloat16 g_chi[(size_t)NM*NE];     // ctx [B,S,E] bf16 hi/lo
__device__ __nv_bfloat16 g_clo[(size_t)NM*NE];

// ---------------------------------------------------------------------------
// Helpers
// ---------------------------------------------------------------------------
__device__ __forceinline__ unsigned smem_u32(const void* p) {
    unsigned a;
    asm("{ .reg .u64 t; cvta.to.shared.u64 t, %1; cvt.u32.u64 %0, t; }"
        : "=r"(a) : "l"(p));
    return a;
}
#define SW128(o) ((o) ^ (((o) >> 3) & 0x70))

__device__ __forceinline__ void ldm4(unsigned* r, unsigned addr) {
    asm volatile("ldmatrix.sync.aligned.m8n8.x4.shared.b16 {%0,%1,%2,%3}, [%4];"
                 : "=r"(r[0]), "=r"(r[1]), "=r"(r[2]), "=r"(r[3]) : "r"(addr));
}
__device__ __forceinline__ void ldm4t(unsigned* r, unsigned addr) {
    asm volatile("ldmatrix.sync.aligned.m8n8.x4.trans.shared.b16 {%0,%1,%2,%3}, [%4];"
                 : "=r"(r[0]), "=r"(r[1]), "=r"(r[2]), "=r"(r[3]) : "r"(addr));
}
__device__ __forceinline__ void mma16816(float* d, unsigned a0, unsigned a1,
                                         unsigned a2, unsigned a3,
                                         unsigned b0, unsigned b1) {
    asm volatile(
        "mma.sync.aligned.m16n8k16.row.col.f32.bf16.bf16.f32 "
        "{%0,%1,%2,%3}, {%4,%5,%6,%7}, {%8,%9}, {%0,%1,%2,%3};"
        : "+f"(d[0]), "+f"(d[1]), "+f"(d[2]), "+f"(d[3])
        : "r"(a0), "r"(a1), "r"(a2), "r"(a3), "r"(b0), "r"(b1));
}
__device__ __forceinline__ void mma16816h(float* d, unsigned a0, unsigned a1,
                                          unsigned a2, unsigned a3,
                                          unsigned b0, unsigned b1) {
    asm volatile(
        "mma.sync.aligned.m16n8k16.row.col.f32.f16.f16.f32 "
        "{%0,%1,%2,%3}, {%4,%5,%6,%7}, {%8,%9}, {%0,%1,%2,%3};"
        : "+f"(d[0]), "+f"(d[1]), "+f"(d[2]), "+f"(d[3])
        : "r"(a0), "r"(a1), "r"(a2), "r"(a3), "r"(b0), "r"(b1));
}
#define CP_ASYNC16(dst, src) \
    asm volatile("cp.async.cg.shared.global [%0], [%1], 16;" :: "r"(dst), "l"(src))
#define CP_COMMIT() asm volatile("cp.async.commit_group;" ::: "memory")
#define CP_WAIT(n)  asm volatile("cp.async.wait_group %0;" :: "n"(n) : "memory")

__device__ __forceinline__ unsigned pack_h2(float a, float b) {
    __half2 t = __floats2half2_rn(a, b);
    return *(unsigned*)&t;
}
__device__ __forceinline__ float ex2(float x) {
    float y;
    asm("ex2.approx.f32 %0, %1;" : "=f"(y) : "f"(x));
    return y;
}

// ---------------------------------------------------------------------------
// fp32 -> bf16 hi/lo splits (GEMM inputs)
// ---------------------------------------------------------------------------
__global__ __launch_bounds__(256)
void split_x_kernel(const float* __restrict__ src)
{
    size_t i = ((size_t)blockIdx.x * 256 + threadIdx.x) * 4;
    float4 v = *(const float4*)(src + i);
    __nv_bfloat16 h0 = __float2bfloat16(v.x), h1 = __float2bfloat16(v.y);
    __nv_bfloat16 h2 = __float2bfloat16(v.z), h3 = __float2bfloat16(v.w);
    *(__nv_bfloat162*)(g_xhi + i)     = __halves2bfloat162(h0, h1);
    *(__nv_bfloat162*)(g_xhi + i + 2) = __halves2bfloat162(h2, h3);
    *(__nv_bfloat162*)(g_xlo + i)     = __halves2bfloat162(
        __float2bfloat16(v.x - __bfloat162float(h0)),
        __float2bfloat16(v.y - __bfloat162float(h1)));
    *(__nv_bfloat162*)(g_xlo + i + 2) = __halves2bfloat162(
        __float2bfloat16(v.z - __bfloat162float(h2)),
        __float2bfloat16(v.w - __bfloat162float(h3)));
}

__global__ __launch_bounds__(256)
void split_w_kernel(const float* __restrict__ Wq, const float* __restrict__ Wk,
                    const float* __restrict__ Wv, const float* __restrict__ Wo)
{
    const float* src = (blockIdx.y == 0) ? Wq : (blockIdx.y == 1) ? Wk
                     : (blockIdx.y == 2) ? Wv : Wo;
    __nv_bfloat16* hi = g_whi + (size_t)blockIdx.y * NE * NE;
    __nv_bfloat16* lo = g_wlo + (size_t)blockIdx.y * NE * NE;
    size_t i = ((size_t)blockIdx.x * 256 + threadIdx.x) * 4;
    float4 v = *(const float4*)(src + i);
    __nv_bfloat16 h0 = __float2bfloat16(v.x), h1 = __float2bfloat16(v.y);
    __nv_bfloat16 h2 = __float2bfloat16(v.z), h3 = __float2bfloat16(v.w);
    *(__nv_bfloat162*)(hi + i)     = __halves2bfloat162(h0, h1);
    *(__nv_bfloat162*)(hi + i + 2) = __halves2bfloat162(h2, h3);
    *(__nv_bfloat162*)(lo + i)     = __halves2bfloat162(
        __float2bfloat16(v.x - __bfloat162float(h0)),
        __float2bfloat16(v.y - __bfloat162float(h1)));
    *(__nv_bfloat162*)(lo + i + 2) = __halves2bfloat162(
        __float2bfloat16(v.z - __bfloat162float(h2)),
        __float2bfloat16(v.w - __bfloat162float(h3)));
}

// ---------------------------------------------------------------------------
// mma.sync NT-GEMM: C[128x128] = A[128xK] @ W[128xK]^T, 3xBF16 split.
// 256 thr = 8 warps (4m x 2n). 3-stage cp.async pipeline.
// mode 0 epilogue -> fp16 singles q/k/v (head-split). mode 1 -> fp32 out.
// ---------------------------------------------------------------------------
#define MM_TILE  16384                 // 128 rows x 128 bytes
#define MM_STAGE (4 * MM_TILE)         // Ah, Al, Bh, Bl (64 KB)
#define MM_SMEM  (3 * MM_STAGE)        // 192 KB, 3 stages

__global__ __launch_bounds__(256, 1)
void mm_tc(int mode, const float* __restrict__ bias0, const float* __restrict__ bias1,
           const float* __restrict__ bias2, float* __restrict__ outp)
{
    extern __shared__ char sm[];
    const unsigned smb = smem_u32(sm);
    const int tid = threadIdx.x;
    const int lane = tid & 31, w = tid >> 5;
    const int wm = w & 3, wn = w >> 2;

    const int z  = (mode == 0) ? (int)blockIdx.z : 3;
    const int m0 = blockIdx.x * 128;
    const int n0 = blockIdx.y * 128;

    const __nv_bfloat16* Ahi = (mode == 0) ? g_xhi : g_chi;
    const __nv_bfloat16* Alo = (mode == 0) ? g_xlo : g_clo;
    const __nv_bfloat16* Bhi = g_whi + (size_t)z * NE * NE;
    const __nv_bfloat16* Blo = g_wlo + (size_t)z * NE * NE;

    const __nv_bfloat16* gp[4] = {
        Ahi + (size_t)m0 * NE, Alo + (size_t)m0 * NE,
        Bhi + (size_t)n0 * NE, Blo + (size_t)n0 * NE };

    float acc[2][8][4];
    #pragma unroll
    for (int mt = 0; mt < 2; mt++)
        #pragma unroll
        for (int nt = 0; nt < 8; nt++)
            #pragma unroll
            for (int q = 0; q < 4; q++) acc[mt][nt][q] = 0.f;

    auto load_chunk = [&](int buf, int k0) {
        const unsigned sb = smb + buf * MM_STAGE;
        #pragma unroll
        for (int t = 0; t < 4; t++)
            #pragma unroll
            for (int i = 0; i < 4; i++) {
                int e = tid + i * 256;
                int r = e >> 3, c = e & 7;
                CP_ASYNC16(sb + t * MM_TILE + SW128(r * 128 + c * 16),
                           gp[t] + (size_t)r * NE + k0 + c * 8);
            }
    };

    load_chunk(0, 0);    CP_COMMIT();
    load_chunk(1, 64);   CP_COMMIT();
    load_chunk(2, 128);  CP_COMMIT();

    int st = 0;
    #pragma unroll 1
    for (int ch = 0; ch < 16; ch++) {
        CP_WAIT(2);
        __syncthreads();

        const unsigned ab = smb + st * MM_STAGE;
        #pragma unroll
        for (int ks = 0; ks < 4; ks++) {
            const unsigned kb = ks * 32 + ((lane >> 4) << 4);
            unsigned ah[2][4], al[2][4];
            #pragma unroll
            for (int mt = 0; mt < 2; mt++) {
                unsigned row = wm * 32 + mt * 16 + (lane & 15);
                unsigned so = SW128(row * 128 + kb);
                ldm4(ah[mt], ab + so);
                ldm4(al[mt], ab + MM_TILE + so);
            }
            unsigned bh0[8], bh1[8], bl0[8], bl1[8];
            #pragma unroll
            for (int np = 0; np < 4; np++) {
                unsigned row = wn * 64 + np * 16 + (lane & 15);
                unsigned so = SW128(row * 128 + kb);
                unsigned r[4];
                ldm4(r, ab + 2 * MM_TILE + so);
                bh0[2*np] = r[0]; bh1[2*np] = r[2];
                bh0[2*np+1] = r[1]; bh1[2*np+1] = r[3];
                ldm4(r, ab + 3 * MM_TILE + so);
                bl0[2*np] = r[0]; bl1[2*np] = r[2];
                bl0[2*np+1] = r[1]; bl1[2*np+1] = r[3];
            }
            #pragma unroll
            for (int mt = 0; mt < 2; mt++)
                #pragma unroll
                for (int nt = 0; nt < 8; nt++) {
                    mma16816(acc[mt][nt], ah[mt][0], ah[mt][1], ah[mt][2], ah[mt][3],
                             bh0[nt], bh1[nt]);
                    mma16816(acc[mt][nt], ah[mt][0], ah[mt][1], ah[mt][2], ah[mt][3],
                             bl0[nt], bl1[nt]);
                    mma16816(acc[mt][nt], al[mt][0], al[mt][1], al[mt][2], al[mt][3],
                             bh0[nt], bh1[nt]);
                }
        }

        __syncthreads();
        if (ch + 3 < 16) load_chunk(st, (ch + 3) * 64);
        CP_COMMIT();
        st = (st == 2) ? 0 : st + 1;
    }

    const int g = lane >> 2, c4 = lane & 3;
    #pragma unroll
    for (int mt = 0; mt < 2; mt++) {
        #pragma unroll
        for (int nt = 0; nt < 8; nt++) {
            const int n = n0 + wn * 64 + nt * 8 + 2 * c4;
            const float2 b2 = *(const float2*)&((mode == 1) ? bias0
                                : (z == 0) ? bias0 : (z == 1) ? bias1 : bias2)[n];
            #pragma unroll
            for (int hrow = 0; hrow < 2; hrow++) {
                const int m = m0 + wm * 32 + mt * 16 + g + hrow * 8;
                float v0 = acc[mt][nt][2*hrow + 0] + b2.x;
                float v1 = acc[mt][nt][2*hrow + 1] + b2.y;
                if (mode == 1) {
                    *(float2*)&outp[(size_t)m * NE + n] = make_float2(v0, v1);
                } else {
                    const int bb = m >> 11, s = m & (NS - 1);
                    const int hh = n >> 6, d = n & 63;
                    size_t idx = (((size_t)(bb * NH + hh)) * NS + s) * ND + d;
                    __half* hp = (z == 0) ? g_q16 : (z == 1) ? g_k16 : g_v16;
                    *(__half2*)&hp[idx] = __floats2half2_rn(v0, v1);
                }
            }
        }
    }
}

// ---------------------------------------------------------------------------
// Flash attention, fp16 single-precision path (error budget analysis in
// commit msg): 1-pass QK, 1-pass PV. 256 thr = 8 warps, 16 q-rows/warp,
// k-tiles of 64. Q fragments hoisted. 3-stage cp.async K/V pipeline.
// NO-MAX softmax, per-thread l accumulation, end reduce.
// ---------------------------------------------------------------------------
#define AT_Q  0                        // 16 KB fp16 Q (128 x 128B)
#define AT_KV 16384
#define AT_KVSTAGE 16384               // K 8KB + V 8KB
#define AT_MASK (AT_KV + 3 * AT_KVSTAGE)
#define AT_SMEM (AT_MASK + 3 * 256 + 16)

__global__ __launch_bounds__(256, 1)
void attn_kernel(const int* __restrict__ amask)
{
    extern __shared__ char sm[];
    const unsigned smb = smem_u32(sm);

    const int tid = threadIdx.x;
    const int lane = tid & 31, w = tid >> 5;
    const int g = lane >> 2, c4 = lane & 3;
    const int b = blockIdx.z, h = blockIdx.y;
    const int q0 = blockIdx.x * 128;

    const size_t bh_off = ((size_t)(b * NH + h)) * NS * ND;
    const __half* Qg = g_q16 + bh_off + (size_t)q0 * ND;
    const __half* KVp[2] = { g_k16 + bh_off, g_v16 + bh_off };
    const int* amp = amask + b * NS;

    auto issue_kv = [&](int stage, int k0) {
        const unsigned sb = smb + AT_KV + stage * AT_KVSTAGE;
        #pragma unroll
        for (int t = 0; t < 2; t++)
            #pragma unroll
            for (int i = 0; i < 2; i++) {
                int e = tid + i * 256;
                int r = e >> 3, c = e & 7;
                CP_ASYNC16(sb + t * 8192 + SW128(r * 128 + c * 16),
                           KVp[t] + (size_t)(k0 + r) * 64 + c * 8);
            }
        if (tid < 16)
            CP_ASYNC16(smb + AT_MASK + stage * 256 + tid * 16,
                       amp + k0 + tid * 4);
    };

    issue_kv(0, 0);    CP_COMMIT();
    issue_kv(1, 64);   CP_COMMIT();
    issue_kv(2, 128);  CP_COMMIT();

    // load Q (128 rows x 128B fp16)
    #pragma unroll
    for (int i = 0; i < 4; i++) {
        int e = tid + i * 256;
        int r = e >> 3, c = e & 7;
        *(uint4*)(sm + AT_Q + SW128(r * 128 + c * 16)) =
            *(const uint4*)(Qg + (size_t)r * 64 + c * 8);
    }
    __syncthreads();

    // hoist Q fragments (loop-invariant): 4 ks x 4 regs
    unsigned qf[4][4];
    {
        const unsigned qrow = w * 16 + (lane & 15);
        #pragma unroll
        for (int ks = 0; ks < 4; ks++) {
            const unsigned kb = ks * 32 + ((lane >> 4) << 4);
            ldm4(qf[ks], smb + AT_Q + SW128(qrow * 128 + kb));
        }
    }

    const float SC = 0.125f * 1.44269504088896f;   // /sqrt(64) * log2(e)
    float l0 = 0.f, l1 = 0.f;
    float o[8][4];
    #pragma unroll
    for (int nt = 0; nt < 8; nt++)
        #pragma unroll
        for (int q = 0; q < 4; q++) o[nt][q] = 0.f;

    int st = 0;
    #pragma unroll 1
    for (int kt = 0; kt < NS / 64; kt++) {
        const unsigned kvb = smb + AT_KV + st * AT_KVSTAGE;
        CP_WAIT(2);
        __syncthreads();

        // ---- S = Q K^T (fp16 single pass) ----
        float s[8][4];
        #pragma unroll
        for (int nt = 0; nt < 8; nt++)
            #pragma unroll
            for (int q = 0; q < 4; q++) s[nt][q] = 0.f;

        #pragma unroll
        for (int ks = 0; ks < 4; ks++) {
            const unsigned kb = ks * 32 + ((lane >> 4) << 4);
            unsigned b0[8], b1[8];
            #pragma unroll
            for (int np = 0; np < 4; np++) {
                unsigned nrow = np * 16 + (lane & 15);
                unsigned r[4];
                ldm4(r, kvb + SW128(nrow * 128 + kb));
                b0[2*np] = r[0]; b1[2*np] = r[2];
                b0[2*np+1] = r[1]; b1[2*np+1] = r[3];
            }
            #pragma unroll
            for (int nt = 0; nt < 8; nt++)
                mma16816h(s[nt], qf[ks][0], qf[ks][1], qf[ks][2], qf[ks][3],
                          b0[nt], b1[nt]);
        }

        // ---- no-max softmax: p = ex2(S*SC + mask), fp16 pack ----
        const int* smask = (const int*)(sm + AT_MASK + st * 256);
        unsigned pg[8], pg8[8];
        #pragma unroll
        for (int nt = 0; nt < 8; nt++) {
            float mA = smask[nt * 8 + 2 * c4]     ? 0.f : -1e30f;
            float mB = smask[nt * 8 + 2 * c4 + 1] ? 0.f : -1e30f;
            float p0 = ex2(fmaf(s[nt][0], SC, mA));
            float p1 = ex2(fmaf(s[nt][1], SC, mB));
            float p2 = ex2(fmaf(s[nt][2], SC, mA));
            float p3 = ex2(fmaf(s[nt][3], SC, mB));
            l0 += p0 + p1;
            l1 += p2 + p3;
            pg[nt]  = pack_h2(p0, p1);
            pg8[nt] = pack_h2(p2, p3);
        }

        // ---- O += P V (fp16 single pass) ----
        #pragma unroll
        for (int j = 0; j < 4; j++) {
            unsigned v0[8], v1[8];
            #pragma unroll
            for (int dp = 0; dp < 4; dp++) {
                unsigned krow = j * 16 + (lane & 7) + ((lane >> 4) << 3);
                unsigned dby  = dp * 32 + (((lane >> 3) & 1) << 4);
                unsigned r[4];
                ldm4t(r, kvb + 8192 + SW128(krow * 128 + dby));
                v0[2*dp] = r[0]; v1[2*dp] = r[2];
                v0[2*dp+1] = r[1]; v1[2*dp+1] = r[3];
            }
            #pragma unroll
            for (int nt = 0; nt < 8; nt++)
                mma16816h(o[nt], pg[2*j], pg8[2*j], pg[2*j+1], pg8[2*j+1],
                          v0[nt], v1[nt]);
        }

        __syncthreads();
        if (kt + 3 < NS / 64) issue_kv(st, (kt + 3) * 64);
        CP_COMMIT();
        st = (st == 2) ? 0 : st + 1;
    }

    // ---- finalize: one cross-lane reduce, normalize, split-write ctx ----
    #pragma unroll
    for (int off = 1; off <= 2; off <<= 1) {
        l0 += __shfl_xor_sync(0xffffffffu, l0, off);
        l1 += __shfl_xor_sync(0xffffffffu, l1, off);
    }
    const float inv0 = 1.0f / l0;
    const float inv1 = 1.0f / l1;
    const int qg = q0 + w * 16 + g;
    #pragma unroll
    for (int nt = 0; nt < 8; nt++) {
        const int col = h * ND + nt * 8 + 2 * c4;
        {
            float v0 = o[nt][0] * inv0, v1 = o[nt][1] * inv0;
            __nv_bfloat16 h0 = __float2bfloat16(v0), h1 = __float2bfloat16(v1);
            size_t idx = ((size_t)(b * NS + qg)) * NE + col;
            *(__nv_bfloat162*)&g_chi[idx] = __halves2bfloat162(h0, h1);
            *(__nv_bfloat162*)&g_clo[idx] = __halves2bfloat162(
                __float2bfloat16(v0 - __bfloat162float(h0)),
                __float2bfloat16(v1 - __bfloat162float(h1)));
        }
        {
            float v0 = o[nt][2] * inv1, v1 = o[nt][3] * inv1;
            __nv_bfloat16 h0 = __float2bfloat16(v0), h1 = __float2bfloat16(v1);
            size_t idx = ((size_t)(b * NS + qg + 8)) * NE + col;
            *(__nv_bfloat162*)&g_chi[idx] = __halves2bfloat162(h0, h1);
            *(__nv_bfloat162*)&g_clo[idx] = __halves2bfloat162(
                __float2bfloat16(v0 - __bfloat162float(h0)),
                __float2bfloat16(v1 - __bfloat162float(h1)));
        }
    }
}

// ---------------------------------------------------------------------------

extern "C" void kernel_launch(void* const* d_in, const int* in_sizes, int n_in,
                              void* d_out, int out_size)
{
    const float* x   = (const float*)d_in[0];
    const int*   am  = (const int*)  d_in[1];
    const float* Wq  = (const float*)d_in[2];
    const float* bq  = (const float*)d_in[3];
    const float* Wk  = (const float*)d_in[4];
    const float* bk  = (const float*)d_in[5];
    const float* Wv  = (const float*)d_in[6];
    const float* bv  = (const float*)d_in[7];
    const float* Wo  = (const float*)d_in[8];
    const float* bo  = (const float*)d_in[9];
    float* out = (float*)d_out;

    cudaFuncSetAttribute(mm_tc, cudaFuncAttributeMaxDynamicSharedMemorySize, MM_SMEM);
    cudaFuncSetAttribute(attn_kernel, cudaFuncAttributeMaxDynamicSharedMemorySize, AT_SMEM);

    split_x_kernel<<<NM * NE / 1024, 256>>>(x);
    split_w_kernel<<<dim3(NE * NE / 1024, 4), 256>>>(Wq, Wk, Wv, Wo);

    mm_tc<<<dim3(NM / 128, NE / 128, 3), 256, MM_SMEM>>>(0, bq, bk, bv, nullptr);

    attn_kernel<<<dim3(NS / 128, NH, NB), 256, AT_SMEM>>>(am);

    mm_tc<<<dim3(NM / 128, NE / 128, 1), 256, MM_SMEM>>>(1, bo, nullptr, nullptr, out);
}

// round 14
// speedup vs baseline: 2.4130x; 1.7239x over previous
#include <cuda_runtime.h>
#include <cuda_bf16.h>
#include <cuda_fp16.h>

#define NB 4
#define NS 2048
#define NE 1024
#define NH 16
#define ND 64
#define NM (NB*NS)          // 8192 rows

// ---------------------------------------------------------------------------
// Device-global scratch (allocation-free rule). All fp16 singles.
// ---------------------------------------------------------------------------
__device__ __half g_x16[(size_t)NM*NE];
__device__ __half g_w16[(size_t)4*NE*NE];          // q,k,v,o
__device__ __half g_q16[(size_t)NM*NE];            // [B,H,S,D]
__device__ __half g_k16[(size_t)NM*NE];
__device__ __half g_v16[(size_t)NM*NE];
__device__ __half g_c16[(size_t)NM*NE];            // ctx [B,S,E]

// ---------------------------------------------------------------------------
// Helpers
// ---------------------------------------------------------------------------
__device__ __forceinline__ unsigned smem_u32(const void* p) {
    unsigned a;
    asm("{ .reg .u64 t; cvta.to.shared.u64 t, %1; cvt.u32.u64 %0, t; }"
        : "=r"(a) : "l"(p));
    return a;
}
#define SW128(o) ((o) ^ (((o) >> 3) & 0x70))

__device__ __forceinline__ void ldm4(unsigned* r, unsigned addr) {
    asm volatile("ldmatrix.sync.aligned.m8n8.x4.shared.b16 {%0,%1,%2,%3}, [%4];"
                 : "=r"(r[0]), "=r"(r[1]), "=r"(r[2]), "=r"(r[3]) : "r"(addr));
}
__device__ __forceinline__ void ldm4t(unsigned* r, unsigned addr) {
    asm volatile("ldmatrix.sync.aligned.m8n8.x4.trans.shared.b16 {%0,%1,%2,%3}, [%4];"
                 : "=r"(r[0]), "=r"(r[1]), "=r"(r[2]), "=r"(r[3]) : "r"(addr));
}
__device__ __forceinline__ void mma16816h(float* d, unsigned a0, unsigned a1,
                                          unsigned a2, unsigned a3,
                                          unsigned b0, unsigned b1) {
    asm volatile(
        "mma.sync.aligned.m16n8k16.row.col.f32.f16.f16.f32 "
        "{%0,%1,%2,%3}, {%4,%5,%6,%7}, {%8,%9}, {%0,%1,%2,%3};"
        : "+f"(d[0]), "+f"(d[1]), "+f"(d[2]), "+f"(d[3])
        : "r"(a0), "r"(a1), "r"(a2), "r"(a3), "r"(b0), "r"(b1));
}
#define CP_ASYNC16(dst, src) \
    asm volatile("cp.async.cg.shared.global [%0], [%1], 16;" :: "r"(dst), "l"(src))
#define CP_COMMIT() asm volatile("cp.async.commit_group;" ::: "memory")
#define CP_WAIT(n)  asm volatile("cp.async.wait_group %0;" :: "n"(n) : "memory")

__device__ __forceinline__ unsigned pack_h2(float a, float b) {
    __half2 t = __floats2half2_rn(a, b);
    return *(unsigned*)&t;
}
__device__ __forceinline__ float ex2(float x) {
    float y;
    asm("ex2.approx.f32 %0, %1;" : "=f"(y) : "f"(x));
    return y;
}

// ---------------------------------------------------------------------------
// fp32 -> fp16 conversions
// ---------------------------------------------------------------------------
__global__ __launch_bounds__(256)
void conv_x_kernel(const float* __restrict__ src)
{
    size_t i = ((size_t)blockIdx.x * 256 + threadIdx.x) * 4;
    float4 v = *(const float4*)(src + i);
    *(__half2*)(g_x16 + i)     = __floats2half2_rn(v.x, v.y);
    *(__half2*)(g_x16 + i + 2) = __floats2half2_rn(v.z, v.w);
}

__global__ __launch_bounds__(256)
void conv_w_kernel(const float* __restrict__ Wq, const float* __restrict__ Wk,
                   const float* __restrict__ Wv, const float* __restrict__ Wo)
{
    const float* src = (blockIdx.y == 0) ? Wq : (blockIdx.y == 1) ? Wk
                     : (blockIdx.y == 2) ? Wv : Wo;
    __half* dst = g_w16 + (size_t)blockIdx.y * NE * NE;
    size_t i = ((size_t)blockIdx.x * 256 + threadIdx.x) * 4;
    float4 v = *(const float4*)(src + i);
    *(__half2*)(dst + i)     = __floats2half2_rn(v.x, v.y);
    *(__half2*)(dst + i + 2) = __floats2half2_rn(v.z, v.w);
}

// ---------------------------------------------------------------------------
// mma.sync NT-GEMM: C[128x128] = A[128xK] @ W[128xK]^T, fp16 single-pass.
// 256 thr = 8 warps (4m x 2n), warp 32x64. BK=64. 3-stage cp.async pipeline.
// mode 0: A = x16, W = wq/wk/wv -> fp16 q/k/v head-split.
// mode 1: A = c16, W = wo -> fp32 d_out.
// ---------------------------------------------------------------------------
#define MM_TILE  16384                 // 128 rows x 128 bytes (64 fp16/row)
#define MM_STAGE (2 * MM_TILE)         // A, B (32 KB)
#define MM_SMEM  (3 * MM_STAGE)        // 96 KB, 3 stages

__global__ __launch_bounds__(256, 1)
void mm_tc(int mode, const float* __restrict__ bias0, const float* __restrict__ bias1,
           const float* __restrict__ bias2, float* __restrict__ outp)
{
    extern __shared__ char sm[];
    const unsigned smb = smem_u32(sm);
    const int tid = threadIdx.x;
    const int lane = tid & 31, w = tid >> 5;
    const int wm = w & 3, wn = w >> 2;

    const int z  = (mode == 0) ? (int)blockIdx.z : 3;
    const int m0 = blockIdx.x * 128;
    const int n0 = blockIdx.y * 128;

    const __half* Ap = ((mode == 0) ? g_x16 : g_c16) + (size_t)m0 * NE;
    const __half* Bp = g_w16 + (size_t)z * NE * NE + (size_t)n0 * NE;

    float acc[2][8][4];
    #pragma unroll
    for (int mt = 0; mt < 2; mt++)
        #pragma unroll
        for (int nt = 0; nt < 8; nt++)
            #pragma unroll
            for (int q = 0; q < 4; q++) acc[mt][nt][q] = 0.f;

    auto load_chunk = [&](int buf, int k0) {
        const unsigned sb = smb + buf * MM_STAGE;
        #pragma unroll
        for (int i = 0; i < 4; i++) {
            int e = tid + i * 256;
            int r = e >> 3, c = e & 7;
            unsigned so = SW128(r * 128 + c * 16);
            CP_ASYNC16(sb + so, Ap + (size_t)r * NE + k0 + c * 8);
            CP_ASYNC16(sb + MM_TILE + so, Bp + (size_t)r * NE + k0 + c * 8);
        }
    };

    load_chunk(0, 0);    CP_COMMIT();
    load_chunk(1, 64);   CP_COMMIT();
    load_chunk(2, 128);  CP_COMMIT();

    int st = 0;
    #pragma unroll 1
    for (int ch = 0; ch < 16; ch++) {
        CP_WAIT(2);
        __syncthreads();

        const unsigned ab = smb + st * MM_STAGE;
        #pragma unroll
        for (int ks = 0; ks < 4; ks++) {
            const unsigned kb = ks * 32 + ((lane >> 4) << 4);
            unsigned ah[2][4];
            #pragma unroll
            for (int mt = 0; mt < 2; mt++) {
                unsigned row = wm * 32 + mt * 16 + (lane & 15);
                ldm4(ah[mt], ab + SW128(row * 128 + kb));
            }
            unsigned b0[8], b1[8];
            #pragma unroll
            for (int np = 0; np < 4; np++) {
                unsigned row = wn * 64 + np * 16 + (lane & 15);
                unsigned r[4];
                ldm4(r, ab + MM_TILE + SW128(row * 128 + kb));
                b0[2*np] = r[0]; b1[2*np] = r[2];
                b0[2*np+1] = r[1]; b1[2*np+1] = r[3];
            }
            #pragma unroll
            for (int mt = 0; mt < 2; mt++)
                #pragma unroll
                for (int nt = 0; nt < 8; nt++)
                    mma16816h(acc[mt][nt], ah[mt][0], ah[mt][1], ah[mt][2], ah[mt][3],
                              b0[nt], b1[nt]);
        }

        __syncthreads();
        if (ch + 3 < 16) load_chunk(st, (ch + 3) * 64);
        CP_COMMIT();
        st = (st == 2) ? 0 : st + 1;
    }

    const int g = lane >> 2, c4 = lane & 3;
    #pragma unroll
    for (int mt = 0; mt < 2; mt++) {
        #pragma unroll
        for (int nt = 0; nt < 8; nt++) {
            const int n = n0 + wn * 64 + nt * 8 + 2 * c4;
            const float2 b2 = *(const float2*)&((mode == 1) ? bias0
                                : (z == 0) ? bias0 : (z == 1) ? bias1 : bias2)[n];
            #pragma unroll
            for (int hrow = 0; hrow < 2; hrow++) {
                const int m = m0 + wm * 32 + mt * 16 + g + hrow * 8;
                float v0 = acc[mt][nt][2*hrow + 0] + b2.x;
                float v1 = acc[mt][nt][2*hrow + 1] + b2.y;
                if (mode == 1) {
                    *(float2*)&outp[(size_t)m * NE + n] = make_float2(v0, v1);
                } else {
                    const int bb = m >> 11, s = m & (NS - 1);
                    const int hh = n >> 6, d = n & 63;
                    size_t idx = (((size_t)(bb * NH + hh)) * NS + s) * ND + d;
                    __half* hp = (z == 0) ? g_q16 : (z == 1) ? g_k16 : g_v16;
                    *(__half2*)&hp[idx] = __floats2half2_rn(v0, v1);
                }
            }
        }
    }
}

// ---------------------------------------------------------------------------
// Flash attention, fp16 single path: 1-pass QK, 1-pass PV. 256 thr = 8 warps,
// 16 q-rows/warp, k-tiles of 64. Q fragments hoisted. 3-stage cp.async K/V.
// NO-MAX softmax, per-thread l accumulation, end reduce. ctx -> fp16.
// ---------------------------------------------------------------------------
#define AT_Q  0                        // 16 KB fp16 Q (128 x 128B)
#define AT_KV 16384
#define AT_KVSTAGE 16384               // K 8KB + V 8KB
#define AT_MASK (AT_KV + 3 * AT_KVSTAGE)
#define AT_SMEM (AT_MASK + 3 * 256 + 16)

__global__ __launch_bounds__(256, 1)
void attn_kernel(const int* __restrict__ amask)
{
    extern __shared__ char sm[];
    const unsigned smb = smem_u32(sm);

    const int tid = threadIdx.x;
    const int lane = tid & 31, w = tid >> 5;
    const int g = lane >> 2, c4 = lane & 3;
    const int b = blockIdx.z, h = blockIdx.y;
    const int q0 = blockIdx.x * 128;

    const size_t bh_off = ((size_t)(b * NH + h)) * NS * ND;
    const __half* Qg = g_q16 + bh_off + (size_t)q0 * ND;
    const __half* KVp[2] = { g_k16 + bh_off, g_v16 + bh_off };
    const int* amp = amask + b * NS;

    auto issue_kv = [&](int stage, int k0) {
        const unsigned sb = smb + AT_KV + stage * AT_KVSTAGE;
        #pragma unroll
        for (int t = 0; t < 2; t++)
            #pragma unroll
            for (int i = 0; i < 2; i++) {
                int e = tid + i * 256;
                int r = e >> 3, c = e & 7;
                CP_ASYNC16(sb + t * 8192 + SW128(r * 128 + c * 16),
                           KVp[t] + (size_t)(k0 + r) * 64 + c * 8);
            }
        if (tid < 16)
            CP_ASYNC16(smb + AT_MASK + stage * 256 + tid * 16,
                       amp + k0 + tid * 4);
    };

    issue_kv(0, 0);    CP_COMMIT();
    issue_kv(1, 64);   CP_COMMIT();
    issue_kv(2, 128);  CP_COMMIT();

    // load Q (128 rows x 128B fp16)
    #pragma unroll
    for (int i = 0; i < 4; i++) {
        int e = tid + i * 256;
        int r = e >> 3, c = e & 7;
        *(uint4*)(sm + AT_Q + SW128(r * 128 + c * 16)) =
            *(const uint4*)(Qg + (size_t)r * 64 + c * 8);
    }
    __syncthreads();

    // hoist Q fragments (loop-invariant): 4 ks x 4 regs
    unsigned qf[4][4];
    {
        const unsigned qrow = w * 16 + (lane & 15);
        #pragma unroll
        for (int ks = 0; ks < 4; ks++) {
            const unsigned kb = ks * 32 + ((lane >> 4) << 4);
            ldm4(qf[ks], smb + AT_Q + SW128(qrow * 128 + kb));
        }
    }

    const float SC = 0.125f * 1.44269504088896f;   // /sqrt(64) * log2(e)
    float l0 = 0.f, l1 = 0.f;
    float o[8][4];
    #pragma unroll
    for (int nt = 0; nt < 8; nt++)
        #pragma unroll
        for (int q = 0; q < 4; q++) o[nt][q] = 0.f;

    int st = 0;
    #pragma unroll 1
    for (int kt = 0; kt < NS / 64; kt++) {
        const unsigned kvb = smb + AT_KV + st * AT_KVSTAGE;
        CP_WAIT(2);
        __syncthreads();

        // ---- S = Q K^T (fp16 single pass) ----
        float s[8][4];
        #pragma unroll
        for (int nt = 0; nt < 8; nt++)
            #pragma unroll
            for (int q = 0; q < 4; q++) s[nt][q] = 0.f;

        #pragma unroll
        for (int ks = 0; ks < 4; ks++) {
            const unsigned kb = ks * 32 + ((lane >> 4) << 4);
            unsigned b0[8], b1[8];
            #pragma unroll
            for (int np = 0; np < 4; np++) {
                unsigned nrow = np * 16 + (lane & 15);
                unsigned r[4];
                ldm4(r, kvb + SW128(nrow * 128 + kb));
                b0[2*np] = r[0]; b1[2*np] = r[2];
                b0[2*np+1] = r[1]; b1[2*np+1] = r[3];
            }
            #pragma unroll
            for (int nt = 0; nt < 8; nt++)
                mma16816h(s[nt], qf[ks][0], qf[ks][1], qf[ks][2], qf[ks][3],
                          b0[nt], b1[nt]);
        }

        // ---- no-max softmax: p = ex2(S*SC + mask), fp16 pack ----
        const int* smask = (const int*)(sm + AT_MASK + st * 256);
        unsigned pg[8], pg8[8];
        #pragma unroll
        for (int nt = 0; nt < 8; nt++) {
            float mA = smask[nt * 8 + 2 * c4]     ? 0.f : -1e30f;
            float mB = smask[nt * 8 + 2 * c4 + 1] ? 0.f : -1e30f;
            float p0 = ex2(fmaf(s[nt][0], SC, mA));
            float p1 = ex2(fmaf(s[nt][1], SC, mB));
            float p2 = ex2(fmaf(s[nt][2], SC, mA));
            float p3 = ex2(fmaf(s[nt][3], SC, mB));
            l0 += p0 + p1;
            l1 += p2 + p3;
            pg[nt]  = pack_h2(p0, p1);
            pg8[nt] = pack_h2(p2, p3);
        }

        // ---- O += P V (fp16 single pass) ----
        #pragma unroll
        for (int j = 0; j < 4; j++) {
            unsigned v0[8], v1[8];
            #pragma unroll
            for (int dp = 0; dp < 4; dp++) {
                unsigned krow = j * 16 + (lane & 7) + ((lane >> 4) << 3);
                unsigned dby  = dp * 32 + (((lane >> 3) & 1) << 4);
                unsigned r[4];
                ldm4t(r, kvb + 8192 + SW128(krow * 128 + dby));
                v0[2*dp] = r[0]; v1[2*dp] = r[2];
                v0[2*dp+1] = r[1]; v1[2*dp+1] = r[3];
            }
            #pragma unroll
            for (int nt = 0; nt < 8; nt++)
                mma16816h(o[nt], pg[2*j], pg8[2*j], pg[2*j+1], pg8[2*j+1],
                          v0[nt], v1[nt]);
        }

        __syncthreads();
        if (kt + 3 < NS / 64) issue_kv(st, (kt + 3) * 64);
        CP_COMMIT();
        st = (st == 2) ? 0 : st + 1;
    }

    // ---- finalize: one cross-lane reduce, normalize, fp16 ctx write ----
    #pragma unroll
    for (int off = 1; off <= 2; off <<= 1) {
        l0 += __shfl_xor_sync(0xffffffffu, l0, off);
        l1 += __shfl_xor_sync(0xffffffffu, l1, off);
    }
    const float inv0 = 1.0f / l0;
    const float inv1 = 1.0f / l1;
    const int qg = q0 + w * 16 + g;
    #pragma unroll
    for (int nt = 0; nt < 8; nt++) {
        const int col = h * ND + nt * 8 + 2 * c4;
        *(__half2*)&g_c16[((size_t)(b * NS + qg)) * NE + col] =
            __floats2half2_rn(o[nt][0] * inv0, o[nt][1] * inv0);
        *(__half2*)&g_c16[((size_t)(b * NS + qg + 8)) * NE + col] =
            __floats2half2_rn(o[nt][2] * inv1, o[nt][3] * inv1);
    }
}

// ---------------------------------------------------------------------------

extern "C" void kernel_launch(void* const* d_in, const int* in_sizes, int n_in,
                              void* d_out, int out_size)
{
    const float* x   = (const float*)d_in[0];
    const int*   am  = (const int*)  d_in[1];
    const float* Wq  = (const float*)d_in[2];
    const float* bq  = (const float*)d_in[3];
    const float* Wk  = (const float*)d_in[4];
    const float* bk  = (const float*)d_in[5];
    const float* Wv  = (const float*)d_in[6];
    const float* bv  = (const float*)d_in[7];
    const float* Wo  = (const float*)d_in[8];
    const float* bo  = (const float*)d_in[9];
    float* out = (float*)d_out;

    cudaFuncSetAttribute(mm_tc, cudaFuncAttributeMaxDynamicSharedMemorySize, MM_SMEM);
    cudaFuncSetAttribute(attn_kernel, cudaFuncAttributeMaxDynamicSharedMemorySize, AT_SMEM);

    conv_x_kernel<<<NM * NE / 1024, 256>>>(x);
    conv_w_kernel<<<dim3(NE * NE / 1024, 4), 256>>>(Wq, Wk, Wv, Wo);

    mm_tc<<<dim3(NM / 128, NE / 128, 3), 256, MM_SMEM>>>(0, bq, bk, bv, nullptr);

    attn_kernel<<<dim3(NS / 128, NH, NB), 256, AT_SMEM>>>(am);

    mm_tc<<<dim3(NM / 128, NE / 128, 1), 256, MM_SMEM>>>(1, bo, nullptr, nullptr, out);
}

// round 15
// speedup vs baseline: 2.4384x; 1.0105x over previous
#include <cuda_runtime.h>
#include <cuda_bf16.h>
#include <cuda_fp16.h>

#define NB 4
#define NS 2048
#define NE 1024
#define NH 16
#define ND 64
#define NM (NB*NS)          // 8192 rows

// ---------------------------------------------------------------------------
// Device-global scratch (allocation-free rule). All fp16 singles.
// ---------------------------------------------------------------------------
__device__ __half g_x16[(size_t)NM*NE];
__device__ __half g_w16[(size_t)4*NE*NE];          // q,k,v,o
__device__ __half g_q16[(size_t)NM*NE];            // [B,H,S,D], pre-scaled
__device__ __half g_k16[(size_t)NM*NE];
__device__ __half g_v16[(size_t)NM*NE];
__device__ __half g_c16[(size_t)NM*NE];            // ctx [B,S,E]

// ---------------------------------------------------------------------------
// Helpers
// ---------------------------------------------------------------------------
__device__ __forceinline__ unsigned smem_u32(const void* p) {
    unsigned a;
    asm("{ .reg .u64 t; cvta.to.shared.u64 t, %1; cvt.u32.u64 %0, t; }"
        : "=r"(a) : "l"(p));
    return a;
}
#define SW128(o) ((o) ^ (((o) >> 3) & 0x70))

__device__ __forceinline__ void ldm4(unsigned* r, unsigned addr) {
    asm volatile("ldmatrix.sync.aligned.m8n8.x4.shared.b16 {%0,%1,%2,%3}, [%4];"
                 : "=r"(r[0]), "=r"(r[1]), "=r"(r[2]), "=r"(r[3]) : "r"(addr));
}
__device__ __forceinline__ void ldm4t(unsigned* r, unsigned addr) {
    asm volatile("ldmatrix.sync.aligned.m8n8.x4.trans.shared.b16 {%0,%1,%2,%3}, [%4];"
                 : "=r"(r[0]), "=r"(r[1]), "=r"(r[2]), "=r"(r[3]) : "r"(addr));
}
__device__ __forceinline__ void mma16816h(float* d, unsigned a0, unsigned a1,
                                          unsigned a2, unsigned a3,
                                          unsigned b0, unsigned b1) {
    asm volatile(
        "mma.sync.aligned.m16n8k16.row.col.f32.f16.f16.f32 "
        "{%0,%1,%2,%3}, {%4,%5,%6,%7}, {%8,%9}, {%0,%1,%2,%3};"
        : "+f"(d[0]), "+f"(d[1]), "+f"(d[2]), "+f"(d[3])
        : "r"(a0), "r"(a1), "r"(a2), "r"(a3), "r"(b0), "r"(b1));
}
#define CP_ASYNC16(dst, src) \
    asm volatile("cp.async.cg.shared.global [%0], [%1], 16;" :: "r"(dst), "l"(src))
#define CP_COMMIT() asm volatile("cp.async.commit_group;" ::: "memory")
#define CP_WAIT(n)  asm volatile("cp.async.wait_group %0;" :: "n"(n) : "memory")

__device__ __forceinline__ unsigned pack_h2(float a, float b) {
    __half2 t = __floats2half2_rn(a, b);
    return *(unsigned*)&t;
}

// ---------------------------------------------------------------------------
// fp32 -> fp16 conversions
// ---------------------------------------------------------------------------
__global__ __launch_bounds__(256)
void conv_x_kernel(const float* __restrict__ src)
{
    size_t i = ((size_t)blockIdx.x * 256 + threadIdx.x) * 4;
    float4 v = *(const float4*)(src + i);
    *(__half2*)(g_x16 + i)     = __floats2half2_rn(v.x, v.y);
    *(__half2*)(g_x16 + i + 2) = __floats2half2_rn(v.z, v.w);
}

__global__ __launch_bounds__(256)
void conv_w_kernel(const float* __restrict__ Wq, const float* __restrict__ Wk,
                   const float* __restrict__ Wv, const float* __restrict__ Wo)
{
    const float* src = (blockIdx.y == 0) ? Wq : (blockIdx.y == 1) ? Wk
                     : (blockIdx.y == 2) ? Wv : Wo;
    __half* dst = g_w16 + (size_t)blockIdx.y * NE * NE;
    size_t i = ((size_t)blockIdx.x * 256 + threadIdx.x) * 4;
    float4 v = *(const float4*)(src + i);
    *(__half2*)(dst + i)     = __floats2half2_rn(v.x, v.y);
    *(__half2*)(dst + i + 2) = __floats2half2_rn(v.z, v.w);
}

// ---------------------------------------------------------------------------
// mma.sync NT-GEMM: C[128x128] = A[128xK] @ W[128xK]^T, fp16 single-pass.
// 256 thr = 8 warps (4m x 2n), warp 32x64. BK=64. 3-stage cp.async pipeline.
// mode 0: A = x16, W = wq/wk/wv -> fp16 q/k/v head-split (q pre-scaled).
// mode 1: A = c16, W = wo -> fp32 d_out.
// ---------------------------------------------------------------------------
#define MM_TILE  16384                 // 128 rows x 128 bytes (64 fp16/row)
#define MM_STAGE (2 * MM_TILE)         // A, B (32 KB)
#define MM_SMEM  (3 * MM_STAGE)        // 96 KB, 3 stages

__global__ __launch_bounds__(256, 1)
void mm_tc(int mode, const float* __restrict__ bias0, const float* __restrict__ bias1,
           const float* __restrict__ bias2, float* __restrict__ outp)
{
    extern __shared__ char sm[];
    const unsigned smb = smem_u32(sm);
    const int tid = threadIdx.x;
    const int lane = tid & 31, w = tid >> 5;
    const int wm = w & 3, wn = w >> 2;

    const int z  = (mode == 0) ? (int)blockIdx.z : 3;
    const int m0 = blockIdx.x * 128;
    const int n0 = blockIdx.y * 128;

    const __half* Ap = ((mode == 0) ? g_x16 : g_c16) + (size_t)m0 * NE;
    const __half* Bp = g_w16 + (size_t)z * NE * NE + (size_t)n0 * NE;

    float acc[2][8][4];
    #pragma unroll
    for (int mt = 0; mt < 2; mt++)
        #pragma unroll
        for (int nt = 0; nt < 8; nt++)
            #pragma unroll
            for (int q = 0; q < 4; q++) acc[mt][nt][q] = 0.f;

    auto load_chunk = [&](int buf, int k0) {
        const unsigned sb = smb + buf * MM_STAGE;
        #pragma unroll
        for (int i = 0; i < 4; i++) {
            int e = tid + i * 256;
            int r = e >> 3, c = e & 7;
            unsigned so = SW128(r * 128 + c * 16);
            CP_ASYNC16(sb + so, Ap + (size_t)r * NE + k0 + c * 8);
            CP_ASYNC16(sb + MM_TILE + so, Bp + (size_t)r * NE + k0 + c * 8);
        }
    };

    load_chunk(0, 0);    CP_COMMIT();
    load_chunk(1, 64);   CP_COMMIT();
    load_chunk(2, 128);  CP_COMMIT();

    int st = 0;
    #pragma unroll 1
    for (int ch = 0; ch < 16; ch++) {
        CP_WAIT(2);
        __syncthreads();

        const unsigned ab = smb + st * MM_STAGE;
        #pragma unroll
        for (int ks = 0; ks < 4; ks++) {
            const unsigned kb = ks * 32 + ((lane >> 4) << 4);
            unsigned ah[2][4];
            #pragma unroll
            for (int mt = 0; mt < 2; mt++) {
                unsigned row = wm * 32 + mt * 16 + (lane & 15);
                ldm4(ah[mt], ab + SW128(row * 128 + kb));
            }
            unsigned b0[8], b1[8];
            #pragma unroll
            for (int np = 0; np < 4; np++) {
                unsigned row = wn * 64 + np * 16 + (lane & 15);
                unsigned r[4];
                ldm4(r, ab + MM_TILE + SW128(row * 128 + kb));
                b0[2*np] = r[0]; b1[2*np] = r[2];
                b0[2*np+1] = r[1]; b1[2*np+1] = r[3];
            }
            #pragma unroll
            for (int mt = 0; mt < 2; mt++)
                #pragma unroll
                for (int nt = 0; nt < 8; nt++)
                    mma16816h(acc[mt][nt], ah[mt][0], ah[mt][1], ah[mt][2], ah[mt][3],
                              b0[nt], b1[nt]);
        }

        __syncthreads();
        if (ch + 3 < 16) load_chunk(st, (ch + 3) * 64);
        CP_COMMIT();
        st = (st == 2) ? 0 : st + 1;
    }

    // scale folded into Q: S*log2e/sqrt(d) done here once
    const float qscale = (mode == 0 && z == 0) ? (0.125f * 1.44269504088896f) : 1.0f;

    const int g = lane >> 2, c4 = lane & 3;
    #pragma unroll
    for (int mt = 0; mt < 2; mt++) {
        #pragma unroll
        for (int nt = 0; nt < 8; nt++) {
            const int n = n0 + wn * 64 + nt * 8 + 2 * c4;
            const float2 b2 = *(const float2*)&((mode == 1) ? bias0
                                : (z == 0) ? bias0 : (z == 1) ? bias1 : bias2)[n];
            #pragma unroll
            for (int hrow = 0; hrow < 2; hrow++) {
                const int m = m0 + wm * 32 + mt * 16 + g + hrow * 8;
                float v0 = acc[mt][nt][2*hrow + 0] + b2.x;
                float v1 = acc[mt][nt][2*hrow + 1] + b2.y;
                if (mode == 1) {
                    *(float2*)&outp[(size_t)m * NE + n] = make_float2(v0, v1);
                } else {
                    v0 *= qscale; v1 *= qscale;
                    const int bb = m >> 11, s = m & (NS - 1);
                    const int hh = n >> 6, d = n & 63;
                    size_t idx = (((size_t)(bb * NH + hh)) * NS + s) * ND + d;
                    __half* hp = (z == 0) ? g_q16 : (z == 1) ? g_k16 : g_v16;
                    *(__half2*)&hp[idx] = __floats2half2_rn(v0, v1);
                }
            }
        }
    }
}

// ---------------------------------------------------------------------------
// Flash attention, fp16 single path: 1-pass QK, 1-pass PV. 256 thr = 8 warps,
// 16 q-rows/warp, k-tiles of 64. Q pre-scaled by log2e/sqrt(d).
// Softmax in fp16x2: pack S, add {-65504,0} mask pair, ex2.approx.f16x2.
// l computed by ones-column MMA on the same fp16 P fragments (error
// cancellation between numerator and denominator; no end shuffle reduce).
// 3-stage cp.async K/V pipeline. ctx -> fp16.
// ---------------------------------------------------------------------------
#define AT_Q  0                        // 16 KB fp16 Q (128 x 128B)
#define AT_KV 16384
#define AT_KVSTAGE 16384               // K 8KB + V 8KB
#define AT_MASK (AT_KV + 3 * AT_KVSTAGE)
#define AT_SMEM (AT_MASK + 3 * 256 + 16)

__global__ __launch_bounds__(256, 1)
void attn_kernel(const int* __restrict__ amask)
{
    extern __shared__ char sm[];
    const unsigned smb = smem_u32(sm);

    const int tid = threadIdx.x;
    const int lane = tid & 31, w = tid >> 5;
    const int g = lane >> 2, c4 = lane & 3;
    const int b = blockIdx.z, h = blockIdx.y;
    const int q0 = blockIdx.x * 128;

    const size_t bh_off = ((size_t)(b * NH + h)) * NS * ND;
    const __half* Qg = g_q16 + bh_off + (size_t)q0 * ND;
    const __half* KVp[2] = { g_k16 + bh_off, g_v16 + bh_off };
    const int* amp = amask + b * NS;

    auto issue_kv = [&](int stage, int k0) {
        const unsigned sb = smb + AT_KV + stage * AT_KVSTAGE;
        #pragma unroll
        for (int t = 0; t < 2; t++)
            #pragma unroll
            for (int i = 0; i < 2; i++) {
                int e = tid + i * 256;
                int r = e >> 3, c = e & 7;
                CP_ASYNC16(sb + t * 8192 + SW128(r * 128 + c * 16),
                           KVp[t] + (size_t)(k0 + r) * 64 + c * 8);
            }
        if (tid < 16)
            CP_ASYNC16(smb + AT_MASK + stage * 256 + tid * 16,
                       amp + k0 + tid * 4);
    };

    issue_kv(0, 0);    CP_COMMIT();
    issue_kv(1, 64);   CP_COMMIT();
    issue_kv(2, 128);  CP_COMMIT();

    // load Q (128 rows x 128B fp16)
    #pragma unroll
    for (int i = 0; i < 4; i++) {
        int e = tid + i * 256;
        int r = e >> 3, c = e & 7;
        *(uint4*)(sm + AT_Q + SW128(r * 128 + c * 16)) =
            *(const uint4*)(Qg + (size_t)r * 64 + c * 8);
    }
    __syncthreads();

    // hoist Q fragments (loop-invariant): 4 ks x 4 regs
    unsigned qf[4][4];
    {
        const unsigned qrow = w * 16 + (lane & 15);
        #pragma unroll
        for (int ks = 0; ks < 4; ks++) {
            const unsigned kb = ks * 32 + ((lane >> 4) << 4);
            ldm4(qf[ks], smb + AT_Q + SW128(qrow * 128 + kb));
        }
    }

    const unsigned ONES = 0x3C003C00u;     // fp16x2 {1,1}
    float lacc[4] = {0.f, 0.f, 0.f, 0.f};  // ones-column row sums
    float o[8][4];
    #pragma unroll
    for (int nt = 0; nt < 8; nt++)
        #pragma unroll
        for (int q = 0; q < 4; q++) o[nt][q] = 0.f;

    int st = 0;
    #pragma unroll 1
    for (int kt = 0; kt < NS / 64; kt++) {
        const unsigned kvb = smb + AT_KV + st * AT_KVSTAGE;
        CP_WAIT(2);
        __syncthreads();

        // ---- S = Q K^T (fp16 single pass; Q pre-scaled) ----
        float s[8][4];
        #pragma unroll
        for (int nt = 0; nt < 8; nt++)
            #pragma unroll
            for (int q = 0; q < 4; q++) s[nt][q] = 0.f;

        #pragma unroll
        for (int ks = 0; ks < 4; ks++) {
            const unsigned kb = ks * 32 + ((lane >> 4) << 4);
            unsigned b0[8], b1[8];
            #pragma unroll
            for (int np = 0; np < 4; np++) {
                unsigned nrow = np * 16 + (lane & 15);
                unsigned r[4];
                ldm4(r, kvb + SW128(nrow * 128 + kb));
                b0[2*np] = r[0]; b1[2*np] = r[2];
                b0[2*np+1] = r[1]; b1[2*np+1] = r[3];
            }
            #pragma unroll
            for (int nt = 0; nt < 8; nt++)
                mma16816h(s[nt], qf[ks][0], qf[ks][1], qf[ks][2], qf[ks][3],
                          b0[nt], b1[nt]);
        }

        // ---- fp16x2 softmax: pack, +mask pair, ex2.f16x2 ----
        const int* smask = (const int*)(sm + AT_MASK + st * 256);
        unsigned pg[8], pg8[8];
        #pragma unroll
        for (int nt = 0; nt < 8; nt++) {
            int2 mi = *(const int2*)&smask[nt * 8 + 2 * c4];
            unsigned msk = (mi.x ? 0u : 0xFBFFu) | (mi.y ? 0u : 0xFBFF0000u);
            unsigned sp0 = pack_h2(s[nt][0], s[nt][1]);
            unsigned sp1 = pack_h2(s[nt][2], s[nt][3]);
            asm("add.rn.f16x2 %0, %0, %1;" : "+r"(sp0) : "r"(msk));
            asm("add.rn.f16x2 %0, %0, %1;" : "+r"(sp1) : "r"(msk));
            asm("ex2.approx.f16x2 %0, %0;" : "+r"(sp0));
            asm("ex2.approx.f16x2 %0, %0;" : "+r"(sp1));
            pg[nt] = sp0; pg8[nt] = sp1;
        }

        // ---- O += P V, l += P 1 (fp16 single pass) ----
        #pragma unroll
        for (int j = 0; j < 4; j++) {
            unsigned v0[8], v1[8];
            #pragma unroll
            for (int dp = 0; dp < 4; dp++) {
                unsigned krow = j * 16 + (lane & 7) + ((lane >> 4) << 3);
                unsigned dby  = dp * 32 + (((lane >> 3) & 1) << 4);
                unsigned r[4];
                ldm4t(r, kvb + 8192 + SW128(krow * 128 + dby));
                v0[2*dp] = r[0]; v1[2*dp] = r[2];
                v0[2*dp+1] = r[1]; v1[2*dp+1] = r[3];
            }
            #pragma unroll
            for (int nt = 0; nt < 8; nt++)
                mma16816h(o[nt], pg[2*j], pg8[2*j], pg[2*j+1], pg8[2*j+1],
                          v0[nt], v1[nt]);
            mma16816h(lacc, pg[2*j], pg8[2*j], pg[2*j+1], pg8[2*j+1],
                      ONES, ONES);
        }

        __syncthreads();
        if (kt + 3 < NS / 64) issue_kv(st, (kt + 3) * 64);
        CP_COMMIT();
        st = (st == 2) ? 0 : st + 1;
    }

    // ---- finalize: l already fully reduced by ones-MMA ----
    const float inv0 = 1.0f / lacc[0];
    const float inv1 = 1.0f / lacc[2];
    const int qg = q0 + w * 16 + g;
    #pragma unroll
    for (int nt = 0; nt < 8; nt++) {
        const int col = h * ND + nt * 8 + 2 * c4;
        *(__half2*)&g_c16[((size_t)(b * NS + qg)) * NE + col] =
            __floats2half2_rn(o[nt][0] * inv0, o[nt][1] * inv0);
        *(__half2*)&g_c16[((size_t)(b * NS + qg + 8)) * NE + col] =
            __floats2half2_rn(o[nt][2] * inv1, o[nt][3] * inv1);
    }
}

// ---------------------------------------------------------------------------

extern "C" void kernel_launch(void* const* d_in, const int* in_sizes, int n_in,
                              void* d_out, int out_size)
{
    const float* x   = (const float*)d_in[0];
    const int*   am  = (const int*)  d_in[1];
    const float* Wq  = (const float*)d_in[2];
    const float* bq  = (const float*)d_in[3];
    const float* Wk  = (const float*)d_in[4];
    const float* bk  = (const float*)d_in[5];
    const float* Wv  = (const float*)d_in[6];
    const float* bv  = (const float*)d_in[7];
    const float* Wo  = (const float*)d_in[8];
    const float* bo  = (const float*)d_in[9];
    float* out = (float*)d_out;

    cudaFuncSetAttribute(mm_tc, cudaFuncAttributeMaxDynamicSharedMemorySize, MM_SMEM);
    cudaFuncSetAttribute(attn_kernel, cudaFuncAttributeMaxDynamicSharedMemorySize, AT_SMEM);

    conv_x_kernel<<<NM * NE / 1024, 256>>>(x);
    conv_w_kernel<<<dim3(NE * NE / 1024, 4), 256>>>(Wq, Wk, Wv, Wo);

    mm_tc<<<dim3(NM / 128, NE / 128, 3), 256, MM_SMEM>>>(0, bq, bk, bv, nullptr);

    attn_kernel<<<dim3(NS / 128, NH, NB), 256, AT_SMEM>>>(am);

    mm_tc<<<dim3(NM / 128, NE / 128, 1), 256, MM_SMEM>>>(1, bo, nullptr, nullptr, out);
}